// round 14
// baseline (speedup 1.0000x reference)
#include <cuda_runtime.h>
#include <math.h>

#define NLEV 16
#define MAX_SIZE (1u << 19)
#define P1 2654435761u
#define P2 805459861u

#define NPTS_MAX 2097152
#define KEY_BITS_DIM 6                   // res-64 Morton key
#define KEY_BITS (3 * KEY_BITS_DIM)      // 18
#define NBINS (1u << KEY_BITS)           // 262144 bins, ~8 pts/bin
#define SCAN_BLK 2048
#define NSCANBLKS (NBINS / SCAN_BLK)     // 128

struct LP {
    float    res[NLEV];
    unsigned mask[NLEV];
};

// Static scratch (allocation-free rule: __device__ globals)
__device__ unsigned d_hist[NBINS];       // becomes intra-block exclusive scan
__device__ unsigned d_bsums[NSCANBLKS];  // exclusive scan of block sums
__device__ unsigned d_packed[NPTS_MAX];  // (rank << 18) | key  per point
__device__ float4   d_sortpt[NPTS_MAX];  // sorted: (x, y, z, orig_idx_bits)

// ---------------- Morton key (6 bits/dim -> 18-bit key) ----------------
__device__ __forceinline__ unsigned expand_bits(unsigned v)
{
    v = (v | (v << 16)) & 0x030000FFu;
    v = (v | (v << 8))  & 0x0300F00Fu;
    v = (v | (v << 4))  & 0x030C30C3u;
    v = (v | (v << 2))  & 0x09249249u;
    return v;
}
__device__ __forceinline__ unsigned morton_key(float px, float py, float pz)
{
    unsigned ix = min(63u, (unsigned)(px * 64.0f));
    unsigned iy = min(63u, (unsigned)(py * 64.0f));
    unsigned iz = min(63u, (unsigned)(pz * 64.0f));
    return expand_bits(ix) | (expand_bits(iy) << 1) | (expand_bits(iz) << 2);
}

// ---------------- Sort pipeline ----------------
// hist: count bins; pack (rank, key) into one word per point.
__global__ void k_hist(const float* __restrict__ x, int n)
{
    int i = blockIdx.x * blockDim.x + threadIdx.x;
    if (i >= n) return;
    unsigned k = morton_key(x[3 * i], x[3 * i + 1], x[3 * i + 2]);
    unsigned r = atomicAdd(&d_hist[k], 1u);
    d_packed[i] = (r << KEY_BITS) | k;
}

__global__ void __launch_bounds__(1024) k_scan1()
{
    __shared__ unsigned s[SCAN_BLK];
    const int t = threadIdx.x;
    const unsigned base = blockIdx.x * SCAN_BLK;
    s[t] = d_hist[base + t];
    s[t + 1024] = d_hist[base + t + 1024];
    int offset = 1;
    for (int d = SCAN_BLK >> 1; d > 0; d >>= 1) {
        __syncthreads();
        if (t < d) {
            int ai = offset * (2 * t + 1) - 1;
            int bi = offset * (2 * t + 2) - 1;
            s[bi] += s[ai];
        }
        offset <<= 1;
    }
    if (t == 0) { d_bsums[blockIdx.x] = s[SCAN_BLK - 1]; s[SCAN_BLK - 1] = 0; }
    for (int d = 1; d < SCAN_BLK; d <<= 1) {
        offset >>= 1;
        __syncthreads();
        if (t < d) {
            int ai = offset * (2 * t + 1) - 1;
            int bi = offset * (2 * t + 2) - 1;
            unsigned tm = s[ai]; s[ai] = s[bi]; s[bi] += tm;
        }
    }
    __syncthreads();
    d_hist[base + t] = s[t];
    d_hist[base + t + 1024] = s[t + 1024];
}

__global__ void __launch_bounds__(128) k_scan2()
{
    __shared__ unsigned s[NSCANBLKS];
    const int t = threadIdx.x;
    s[t] = d_bsums[t];
    __syncthreads();
    unsigned v = s[t];
    for (int d = 1; d < NSCANBLKS; d <<= 1) {
        unsigned add = (t >= d) ? s[t - d] : 0u;
        __syncthreads();
        v += add;
        s[t] = v;
        __syncthreads();
    }
    d_bsums[t] = (t == 0) ? 0u : s[t - 1];
}

// Atomic-free scatter of COORDS+index into sorted order. The 16B random
// writes cost more here, but they convert the encode kernel's random per-point
// x gathers (~3 wavefronts/pt) into one coalesced float4 load.
__global__ void k_scatter(const float* __restrict__ x, int n)
{
    int i = blockIdx.x * blockDim.x + threadIdx.x;
    if (i >= n) return;
    const float px = x[3 * i], py = x[3 * i + 1], pz = x[3 * i + 2];
    const unsigned pk = d_packed[i];
    const unsigned k  = pk & (NBINS - 1u);
    const unsigned r  = pk >> KEY_BITS;
    const unsigned p  = d_hist[k] + d_bsums[k >> 11] + r;
    d_sortpt[p] = make_float4(px, py, pz, __uint_as_float((unsigned)i));
}

// ---------------- Main encode: 2 lanes/point, 16 points/warp, lane = bx ----------------
__global__ void __launch_bounds__(256)
hashgrid_kernel(const float* __restrict__ tables,
                float* __restrict__ out,
                LP lp, int n)
{
    const int lane   = threadIdx.x & 31;
    const int warpid = (blockIdx.x * (blockDim.x >> 5)) + (threadIdx.x >> 5);
    const int ptraw  = warpid * 16 + (lane >> 1);
    const bool valid = ptraw < n;
    const int pt     = valid ? ptraw : (n - 1);   // clamp; lanes stay converged
    const unsigned p = lane & 1;                  // bx for this lane

    // One coalesced/broadcast float4: coords + original index.
    const float4 s4 = __ldg(&d_sortpt[pt]);
    const float px = s4.x, py = s4.y, pz = s4.z;
    const unsigned oidx = __float_as_uint(s4.w);

    // Lane p keeps levels [8p, 8p+8): 8 float2 = 4 float4.
    float rf[16];

#pragma unroll
    for (int l = 0; l < NLEV; ++l) {
        const float    res  = lp.res[l];
        const unsigned mask = lp.mask[l];
        const float2* __restrict__ tbl =
            reinterpret_cast<const float2*>(tables) + (size_t)l * MAX_SIZE;

        const float xs = px * res, ys = py * res, zs = pz * res;
        const float fx = floorf(xs), fy = floorf(ys), fz = floorf(zs);

        const unsigned ix = (unsigned)fx + p;
        const unsigned iy = (unsigned)fy;
        const unsigned iz = (unsigned)fz;

        const float xf = xs - fx, yf = ys - fy, zf = zs - fz;
        const float wx   = p ? xf : (1.0f - xf);
        const float wy0  = 1.0f - yf, wy1 = yf;
        const float wz0  = 1.0f - zf, wz1 = zf;
        const float w00  = wy0 * wz0;
        const float w10  = wy1 * wz0;
        const float w01  = wy0 * wz1;
        const float w11  = wy1 * wz1;

        const unsigned hy0 = iy * P1;
        const unsigned hy1 = hy0 + P1;
        const unsigned hz0 = iz * P2;
        const unsigned hz1 = hz0 + P2;

        const unsigned h00 = (ix ^ hy0 ^ hz0) & mask;
        const unsigned h10 = (ix ^ hy1 ^ hz0) & mask;
        const unsigned h01 = (ix ^ hy0 ^ hz1) & mask;
        const unsigned h11 = (ix ^ hy1 ^ hz1) & mask;

        const float2 f00 = __ldg(&tbl[h00]);
        const float2 f10 = __ldg(&tbl[h10]);
        const float2 f01 = __ldg(&tbl[h01]);
        const float2 f11 = __ldg(&tbl[h11]);

        // accumulate over (by,bz), then scale once by wx
        float ax = w00 * f00.x;
        float ay = w00 * f00.y;
        ax = fmaf(w10, f10.x, ax);
        ay = fmaf(w10, f10.y, ay);
        ax = fmaf(w01, f01.x, ax);
        ay = fmaf(w01, f01.y, ay);
        ax = fmaf(w11, f11.x, ax);
        ay = fmaf(w11, f11.y, ay);

        float vx = wx * ax;
        float vy = wx * ay;

        // sum the two x-halves
        vx += __shfl_xor_sync(0xffffffffu, vx, 1);
        vy += __shfl_xor_sync(0xffffffffu, vy, 1);

        // lane p stashes levels 8p..8p+7
        if ((l >> 3) == (int)p) {
            rf[2 * (l & 7) + 0] = vx;
            rf[2 * (l & 7) + 1] = vy;
        }
    }

    if (valid) {
        float4* o = reinterpret_cast<float4*>(out + (size_t)oidx * 32) + 4 * p;
        o[0] = make_float4(rf[0],  rf[1],  rf[2],  rf[3]);
        o[1] = make_float4(rf[4],  rf[5],  rf[6],  rf[7]);
        o[2] = make_float4(rf[8],  rf[9],  rf[10], rf[11]);
        o[3] = make_float4(rf[12], rf[13], rf[14], rf[15]);
    }
}

extern "C" void kernel_launch(void* const* d_in, const int* in_sizes, int n_in,
                              void* d_out, int out_size)
{
    const float* x      = (const float*)d_in[0];
    const float* tables = (const float*)d_in[1];
    float*       out    = (float*)d_out;
    const int    n      = in_sizes[0] / 3;

    // Replicate the reference's level-resolution math EXACTLY in double precision.
    LP lp;
    const double b = exp((log(512.0) - log(16.0)) / 15.0);
    for (int l = 0; l < NLEV; ++l) {
        const double r   = floor(16.0 * pow(b, (double)l));
        const long   res = (long)r;
        long sz = res * res * res;
        if (sz > (1L << 19)) sz = (1L << 19);
        long p = 1;
        while (p < sz) p <<= 1;
        lp.res[l]  = (float)r;
        lp.mask[l] = (unsigned)(p - 1);
    }

    static void* hist_ptr = nullptr;
    if (!hist_ptr) cudaGetSymbolAddress(&hist_ptr, d_hist);

    // 1) zero histogram (1 MB)
    cudaMemsetAsync(hist_ptr, 0, NBINS * sizeof(unsigned), 0);

    // 2) histogram; pack (rank, key) per point
    k_hist<<<(n + 255) / 256, 256>>>(x, n);

    // 3) two-level exclusive scan
    k_scan1<<<NSCANBLKS, 1024>>>();
    k_scan2<<<1, 128>>>();

    // 4) atomic-free scatter of coords + index into sorted order
    k_scatter<<<(n + 255) / 256, 256>>>(x, n);

    // 5) encode: 16 points per warp, 128 points per 256-thread block
    const int threads = 256;
    const int pts_per_block = (threads / 32) * 16;
    const int blocks = (n + pts_per_block - 1) / pts_per_block;
    hashgrid_kernel<<<blocks, threads>>>(tables, out, lp, n);
}

// round 15
// speedup vs baseline: 1.0148x; 1.0148x over previous
#include <cuda_runtime.h>
#include <math.h>

#define NLEV 16
#define MAX_SIZE (1u << 19)
#define P1 2654435761u
#define P2 805459861u

#define NPTS_MAX 2097152
#define KEY_BITS_DIM 6                   // res-64 Morton key
#define KEY_BITS (3 * KEY_BITS_DIM)      // 18
#define NBINS (1u << KEY_BITS)           // 262144 bins, ~8 pts/bin
#define SCAN_BLK 2048
#define NSCANBLKS (NBINS / SCAN_BLK)     // 128

struct LP {
    float    res[NLEV];
    unsigned mask[NLEV];
};

// Static scratch (allocation-free rule: __device__ globals)
__device__ unsigned d_hist[NBINS];       // becomes intra-block exclusive scan
__device__ unsigned d_bsums[NSCANBLKS];  // exclusive scan of block sums
__device__ unsigned d_packed[NPTS_MAX];  // (rank << 18) | key per point
__device__ unsigned d_perm[NPTS_MAX];    // sorted slot -> original point index

// ---------------- Morton key (6 bits/dim -> 18-bit key) ----------------
__device__ __forceinline__ unsigned expand_bits(unsigned v)
{
    v = (v | (v << 16)) & 0x030000FFu;
    v = (v | (v << 8))  & 0x0300F00Fu;
    v = (v | (v << 4))  & 0x030C30C3u;
    v = (v | (v << 2))  & 0x09249249u;
    return v;
}
__device__ __forceinline__ unsigned morton_key(float px, float py, float pz)
{
    unsigned ix = min(63u, (unsigned)(px * 64.0f));
    unsigned iy = min(63u, (unsigned)(py * 64.0f));
    unsigned iz = min(63u, (unsigned)(pz * 64.0f));
    return expand_bits(ix) | (expand_bits(iy) << 1) | (expand_bits(iz) << 2);
}

// ---------------- Sort pipeline ----------------
__global__ void k_hist(const float* __restrict__ x, int n)
{
    int i = blockIdx.x * blockDim.x + threadIdx.x;
    if (i >= n) return;
    unsigned k = morton_key(x[3 * i], x[3 * i + 1], x[3 * i + 2]);
    unsigned r = atomicAdd(&d_hist[k], 1u);
    d_packed[i] = (r << KEY_BITS) | k;   // rank fits: <= ~40 per bin for uniform input
}

__global__ void __launch_bounds__(1024) k_scan1()
{
    __shared__ unsigned s[SCAN_BLK];
    const int t = threadIdx.x;
    const unsigned base = blockIdx.x * SCAN_BLK;
    s[t] = d_hist[base + t];
    s[t + 1024] = d_hist[base + t + 1024];
    int offset = 1;
    for (int d = SCAN_BLK >> 1; d > 0; d >>= 1) {
        __syncthreads();
        if (t < d) {
            int ai = offset * (2 * t + 1) - 1;
            int bi = offset * (2 * t + 2) - 1;
            s[bi] += s[ai];
        }
        offset <<= 1;
    }
    if (t == 0) { d_bsums[blockIdx.x] = s[SCAN_BLK - 1]; s[SCAN_BLK - 1] = 0; }
    for (int d = 1; d < SCAN_BLK; d <<= 1) {
        offset >>= 1;
        __syncthreads();
        if (t < d) {
            int ai = offset * (2 * t + 1) - 1;
            int bi = offset * (2 * t + 2) - 1;
            unsigned tm = s[ai]; s[ai] = s[bi]; s[bi] += tm;
        }
    }
    __syncthreads();
    d_hist[base + t] = s[t];
    d_hist[base + t + 1024] = s[t + 1024];
}

__global__ void __launch_bounds__(128) k_scan2()
{
    __shared__ unsigned s[NSCANBLKS];
    const int t = threadIdx.x;
    s[t] = d_bsums[t];
    __syncthreads();
    unsigned v = s[t];
    for (int d = 1; d < NSCANBLKS; d <<= 1) {
        unsigned add = (t >= d) ? s[t - d] : 0u;
        __syncthreads();
        v += add;
        s[t] = v;
        __syncthreads();
    }
    d_bsums[t] = (t == 0) ? 0u : s[t - 1];
}

// Atomic-free 4B scatter: slot = local_scan[k] + block_prefix + rank.
__global__ void k_scatter(int n)
{
    int i = blockIdx.x * blockDim.x + threadIdx.x;
    if (i >= n) return;
    const unsigned pk = d_packed[i];
    const unsigned k  = pk & (NBINS - 1u);
    const unsigned r  = pk >> KEY_BITS;
    d_perm[d_hist[k] + d_bsums[k >> 11] + r] = (unsigned)i;
}

// ---------------- Main encode: 2 lanes/point, 16 points/warp, lane = bx ----------------
// x-pair merges inside each LDG wavefront (lane parity = bx). Point coords are
// loaded split across the lane pair (x/z in one instruction, y broadcast) and
// exchanged with one shfl. Output rows are transposed through smem so each
// STG.128 instruction writes only 4 distinct 128B lines (1 store wf/point).
__global__ void __launch_bounds__(256)
hashgrid_kernel(const float* __restrict__ x,
                const float* __restrict__ tables,
                float* __restrict__ out,
                LP lp, int n)
{
    __shared__ float    sbuf[8][16 * 36];   // [warp][point*36 + float]; stride 36 = conflict-free
    __shared__ unsigned soid[8][16];

    const int lane   = threadIdx.x & 31;
    const int w      = threadIdx.x >> 5;
    const int warpid = (blockIdx.x * (blockDim.x >> 5)) + w;
    const int q      = lane >> 1;               // point-local index 0..15
    const int ptraw  = warpid * 16 + q;
    const int pt     = (ptraw < n) ? ptraw : (n - 1);  // clamp; lanes stay converged
    const unsigned p = lane & 1;                // bx for this lane

    const unsigned oidx = __ldg(&d_perm[pt]);

    // Split coord load: lane0 loads x, lane1 loads z (same line 15/16),
    // y is a broadcast load; one shfl exchanges x<->z.
    const float a     = __ldg(&x[3 * oidx + 2 * p]);
    const float py    = __ldg(&x[3 * oidx + 1]);
    const float other = __shfl_xor_sync(0xffffffffu, a, 1);
    const float px = p ? other : a;
    const float pz = p ? a : other;

    // Lane p keeps levels [8p, 8p+8): 8 float2 = 16 floats.
    float rf[16];

#pragma unroll
    for (int l = 0; l < NLEV; ++l) {
        const float    res  = lp.res[l];
        const unsigned mask = lp.mask[l];
        const float2* __restrict__ tbl =
            reinterpret_cast<const float2*>(tables) + (size_t)l * MAX_SIZE;

        const float xs = px * res, ys = py * res, zs = pz * res;
        const float fx = floorf(xs), fy = floorf(ys), fz = floorf(zs);

        const unsigned ix = (unsigned)fx + p;
        const unsigned iy = (unsigned)fy;
        const unsigned iz = (unsigned)fz;

        const float xf = xs - fx, yf = ys - fy, zf = zs - fz;
        const float wx   = p ? xf : (1.0f - xf);
        const float wy0  = 1.0f - yf, wy1 = yf;
        const float wz0  = 1.0f - zf, wz1 = zf;
        const float w00  = wy0 * wz0;
        const float w10  = wy1 * wz0;
        const float w01  = wy0 * wz1;
        const float w11  = wy1 * wz1;

        const unsigned hy0 = iy * P1;
        const unsigned hy1 = hy0 + P1;
        const unsigned hz0 = iz * P2;
        const unsigned hz1 = hz0 + P2;

        const unsigned h00 = (ix ^ hy0 ^ hz0) & mask;
        const unsigned h10 = (ix ^ hy1 ^ hz0) & mask;
        const unsigned h01 = (ix ^ hy0 ^ hz1) & mask;
        const unsigned h11 = (ix ^ hy1 ^ hz1) & mask;

        const float2 f00 = __ldg(&tbl[h00]);
        const float2 f10 = __ldg(&tbl[h10]);
        const float2 f01 = __ldg(&tbl[h01]);
        const float2 f11 = __ldg(&tbl[h11]);

        // accumulate over (by,bz), then scale once by wx
        float ax = w00 * f00.x;
        float ay = w00 * f00.y;
        ax = fmaf(w10, f10.x, ax);
        ay = fmaf(w10, f10.y, ay);
        ax = fmaf(w01, f01.x, ax);
        ay = fmaf(w01, f01.y, ay);
        ax = fmaf(w11, f11.x, ax);
        ay = fmaf(w11, f11.y, ay);

        float vx = wx * ax;
        float vy = wx * ay;

        // sum the two x-halves
        vx += __shfl_xor_sync(0xffffffffu, vx, 1);
        vy += __shfl_xor_sync(0xffffffffu, vy, 1);

        // lane p stashes levels 8p..8p+7
        if ((l >> 3) == (int)p) {
            rf[2 * (l & 7) + 0] = vx;
            rf[2 * (l & 7) + 1] = vy;
        }
    }

    // --- Transposed store: stage row in smem, write 8 lanes per point. ---
    {
        float* row = &sbuf[w][q * 36 + 16 * p];
#pragma unroll
        for (int k = 0; k < 4; ++k)
            *reinterpret_cast<float4*>(row + 4 * k) =
                make_float4(rf[4 * k], rf[4 * k + 1], rf[4 * k + 2], rf[4 * k + 3]);
        if (p == 0) soid[w][q] = oidx;
    }
    __syncwarp();

    {
        const int c = lane & 7;                 // float4 column within the row
#pragma unroll
        for (int s = 0; s < 4; ++s) {
            const int g = 4 * s + (lane >> 3);  // point-local index this lane stores
            if (warpid * 16 + g < n) {
                const float4 v = *reinterpret_cast<const float4*>(&sbuf[w][g * 36 + 4 * c]);
                const unsigned og = soid[w][g];
                reinterpret_cast<float4*>(out + (size_t)og * 32)[c] = v;
            }
        }
    }
}

extern "C" void kernel_launch(void* const* d_in, const int* in_sizes, int n_in,
                              void* d_out, int out_size)
{
    const float* x      = (const float*)d_in[0];
    const float* tables = (const float*)d_in[1];
    float*       out    = (float*)d_out;
    const int    n      = in_sizes[0] / 3;

    // Replicate the reference's level-resolution math EXACTLY in double precision.
    LP lp;
    const double b = exp((log(512.0) - log(16.0)) / 15.0);
    for (int l = 0; l < NLEV; ++l) {
        const double r   = floor(16.0 * pow(b, (double)l));
        const long   res = (long)r;
        long sz = res * res * res;
        if (sz > (1L << 19)) sz = (1L << 19);
        long p = 1;
        while (p < sz) p <<= 1;
        lp.res[l]  = (float)r;
        lp.mask[l] = (unsigned)(p - 1);
    }

    static void* hist_ptr = nullptr;
    if (!hist_ptr) cudaGetSymbolAddress(&hist_ptr, d_hist);

    // 1) zero histogram (1 MB)
    cudaMemsetAsync(hist_ptr, 0, NBINS * sizeof(unsigned), 0);

    // 2) histogram; pack (rank, key) per point
    k_hist<<<(n + 255) / 256, 256>>>(x, n);

    // 3) two-level exclusive scan
    k_scan1<<<NSCANBLKS, 1024>>>();
    k_scan2<<<1, 128>>>();

    // 4) atomic-free 4B perm scatter
    k_scatter<<<(n + 255) / 256, 256>>>(n);

    // 5) encode: 16 points per warp, 128 points per 256-thread block
    const int threads = 256;
    const int pts_per_block = (threads / 32) * 16;
    const int blocks = (n + pts_per_block - 1) / pts_per_block;
    hashgrid_kernel<<<blocks, threads>>>(x, tables, out, lp, n);
}